// round 16
// baseline (speedup 1.0000x reference)
#include <cuda_runtime.h>
#include <math.h>
#include <stdint.h>

#define NC    2048
#define DD    1024
#define HD2   512
#define BB    2
#define HH    8
#define HDIM  128
#define D3    3072
#define INDIM 512

// ----------------------------- device scratch -----------------------------
__device__ float g_ampr0[NC*2*DD];   // reused: walk prob partials (pass 2)
__device__ float g_ampi0[NC*2*DD];   // reused: walk phase partials (pass 2)
__device__ float g_ampr1[NC*2*DD];   // reused: walk prob partials (pass 1)
__device__ float g_ampi1[NC*2*DD];   // reused: walk phase partials (pass 1)
__device__ float g_probs[NC];
__device__ float g_ph[NC];
__device__ float g_wavef[NC];
__device__ float g_cells[NC*DD];
__device__ float g_fmean[8*DD];
__device__ float g_xproj[BB*DD];
__device__ float g_cellsB[BB*NC*DD];
__device__ float g_cellsR[BB*NC*DD];  // tf32-rounded cellsB (GEMM A operand)
__device__ float g_qkv[(size_t)BB*NC*D3];
__device__ float g_scores[(size_t)BB*HH*NC*NC];   // raw exp(S), 256 MiB
__device__ float g_rowsum[BB*HH*NC];
__device__ float g_av[(size_t)BB*NC*DD];
__device__ float g_tmp[(size_t)BB*NC*DD];
__device__ float g_part1[BB*NC];
__device__ float g_part2[BB*NC];
__device__ float g_wqkv[2*D3*DD];     // tf32-rounded attn_in_w
__device__ float g_wout[2*DD*DD];     // tf32-rounded attn_out_w
__device__ float g_wfin[INDIM*DD];    // tf32-rounded w_out
__device__ float g_xmean;
__device__ float g_ptot;
__device__ float g_tension;

// ----------------------------- small kernels ------------------------------
__global__ void k_xmean(const float* __restrict__ x, int n) {
    __shared__ float red[256];
    float s = 0.f;
    for (int i = threadIdx.x; i < n; i += 256) s += x[i];
    red[threadIdx.x] = s; __syncthreads();
    for (int st = 128; st > 0; st >>= 1) {
        if (threadIdx.x < st) red[threadIdx.x] += red[threadIdx.x + st];
        __syncthreads();
    }
    if (threadIdx.x == 0) { g_xmean = red[0] / (float)n; g_tension = 0.f; }
}

__device__ __forceinline__ uint32_t f2tf32(float x) {
    uint32_t r; asm("cvt.rna.tf32.f32 %0, %1;" : "=r"(r) : "f"(x)); return r;
}
__device__ __forceinline__ float tfr(float x) { return __uint_as_float(f2tf32(x)); }

// round-copy weights to tf32 (idempotent w.r.t. in-GEMM cvt)
__global__ void k_roundcpy(float* __restrict__ dst, const float* __restrict__ src, int n4) {
    int i = blockIdx.x * 256 + threadIdx.x;
    if (i < n4) {
        float4 v = ((const float4*)src)[i];
        v.x = tfr(v.x); v.y = tfr(v.y); v.z = tfr(v.z); v.w = tfr(v.w);
        ((float4*)dst)[i] = v;
    }
}

// standing-wave factor table (replaces 16MB cells read-modify-write)
__global__ void k_wavef(const int* __restrict__ step) {
    int i = blockIdx.x*1024 + threadIdx.x;
    float st  = (float)step[0];
    float fwd = fmodf(st * 0.15f, 2048.f);
    float bwd = fmodf(2048.f - st * 0.15f, 2048.f);
    float fi  = (float)i;
    float c1 = coshf((fi - fwd) * 0.5f), c2 = coshf((fi - bwd) * 0.5f);
    g_wavef[i] = 1.f + 0.03f * (1.f/(c1*c1) + 1.f/(c2*c2));
}

// ---- fused double quantum-walk: 512 blocks x 2 columns, dbl-buffered smem --
// Amp intermediate never touches DRAM (dead after this kernel); two partial
// sets written. RC: real-coin fast path (ci == 0, bit-identical).
template<bool RC>
__device__ __forceinline__ void walk_pass(
    const float* __restrict__ sr0, const float* __restrict__ si0,
    const float* __restrict__ sr1, const float* __restrict__ si1,
    float* __restrict__ dr0, float* __restrict__ di0,
    float* __restrict__ dr1, float* __restrict__ di1,
    float c00r, float c00i, float c01r, float c01i,
    float c10r, float c10i, float c11r, float c11i,
    float pc, float ps, int c, int nl, int blk,
    float* __restrict__ pp, float* __restrict__ hp, bool dowrite)
{
    for (int it = 0; it < 16; it++) {
        int n = nl + 128*it;
        int base = n*2 + c;
        float a0r = sr0[base], a0i = si0[base], a1r = sr1[base], a1i = si1[base];
        float n0r, n0i, sr, si;
        if (RC) {
            n0r = c00r*a0r + c01r*a1r;
            n0i = c00r*a0i + c01r*a1i;
            sr = 0.f; si = 0.f;
#pragma unroll
            for (int j = 0; j < 11; j++) {
                int mb = (n ^ (1<<j))*2 + c;
                sr += c10r*sr0[mb] + c11r*sr1[mb];
                si += c10r*si0[mb] + c11r*si1[mb];
            }
        } else {
            n0r = c00r*a0r - c00i*a0i + c01r*a1r - c01i*a1i;
            n0i = c00r*a0i + c00i*a0r + c01r*a1i + c01i*a1r;
            sr = 0.f; si = 0.f;
#pragma unroll
            for (int j = 0; j < 11; j++) {
                int mb = (n ^ (1<<j))*2 + c;
                float x0r = sr0[mb], x0i = si0[mb], x1r = sr1[mb], x1i = si1[mb];
                sr += c10r*x0r - c10i*x0i + c11r*x1r - c11i*x1i;
                si += c10r*x0i + c10i*x0r + c11r*x1i + c11i*x1r;
            }
        }
        float n1r = sr*(1.f/11.f), n1i = si*(1.f/11.f);
        float o0r = n0r*pc - n0i*ps, o0i = n0r*ps + n0i*pc;
        float o1r = n1r*pc - n1i*ps, o1i = n1r*ps + n1i*pc;
        if (dowrite) {
            dr0[base] = o0r; di0[base] = o0i;
            dr1[base] = o1r; di1[base] = o1i;
        }
        float pq = o0r*o0r + o0i*o0i + o1r*o1r + o1i*o1i;
        float hq = atan2f(o0i + o1i, o0r + o1r);
        pq += __shfl_down_sync(0xffffffffu, pq, 1, 2);
        hq += __shfl_down_sync(0xffffffffu, hq, 1, 2);
        if (c == 0) { pp[blk*2048 + n] = pq; hp[blk*2048 + n] = hq; }
    }
}

__global__ void __launch_bounds__(256, 1) k_walk2(
    const float* __restrict__ inr, const float* __restrict__ ini,
    const float* __restrict__ cr, const float* __restrict__ ci,
    float* __restrict__ pp1, float* __restrict__ hp1,
    float* __restrict__ pp2, float* __restrict__ hp2)
{
    extern __shared__ float ws[];
    float* A0r = ws;            float* A0i = ws + 4096;
    float* A1r = ws + 8192;     float* A1i = ws + 12288;
    float* B0r = ws + 16384;    float* B0i = ws + 20480;
    float* B1r = ws + 24576;    float* B1i = ws + 28672;
    int tid = threadIdx.x;
    int d0 = blockIdx.x * 2;
    for (int idx = tid; idx < 4096; idx += 256) {
        int n = idx >> 1, s = idx & 1;
        size_t off = (size_t)(n*2 + s)*DD + d0;
        float2 vr = *(const float2*)(inr + off);
        float2 vi = *(const float2*)(ini + off);
        *(float2*)((s ? A1r : A0r) + n*2) = vr;
        *(float2*)((s ? A1i : A0i) + n*2) = vi;
    }
    __syncthreads();
    float c00r=cr[0], c01r=cr[1], c10r=cr[2], c11r=cr[3];
    float c00i=ci[0], c01i=ci[1], c10i=ci[2], c11i=ci[3];
    bool rc = (c00i==0.f) && (c01i==0.f) && (c10i==0.f) && (c11i==0.f);
    float phi = g_xmean * 0.1f;
    float pc = cosf(phi), ps = sinf(phi);
    int c = tid & 1, nl = tid >> 1;
    int blk = blockIdx.x;
    if (rc) {
        walk_pass<true>(A0r,A0i,A1r,A1i, B0r,B0i,B1r,B1i,
                        c00r,c00i,c01r,c01i,c10r,c10i,c11r,c11i,
                        pc,ps,c,nl,blk, pp1,hp1, true);
        __syncthreads();
        walk_pass<true>(B0r,B0i,B1r,B1i, A0r,A0i,A1r,A1i,
                        c00r,c00i,c01r,c01i,c10r,c10i,c11r,c11i,
                        pc,ps,c,nl,blk, pp2,hp2, false);
    } else {
        walk_pass<false>(A0r,A0i,A1r,A1i, B0r,B0i,B1r,B1i,
                         c00r,c00i,c01r,c01i,c10r,c10i,c11r,c11i,
                         pc,ps,c,nl,blk, pp1,hp1, true);
        __syncthreads();
        walk_pass<false>(B0r,B0i,B1r,B1i, A0r,A0i,A1r,A1i,
                         c00r,c00i,c01r,c01i,c10r,c10i,c11r,c11i,
                         pc,ps,c,nl,blk, pp2,hp2, false);
    }
}

// reduce 512 block-partials per node -> g_probs / g_ph. grid 64 x 256.
__global__ void k_pred(const float* __restrict__ pprt, const float* __restrict__ hprt) {
    __shared__ float sp[256], sh[256];
    int tid = threadIdx.x;
    int n = blockIdx.x*32 + (tid & 31);
    int bg = tid >> 5;
    float p = 0.f, h = 0.f;
    for (int j = 0; j < 64; j++) {
        int b = bg*64 + j;
        p += pprt[b*2048 + n];
        h += hprt[b*2048 + n];
    }
    sp[tid] = p; sh[tid] = h; __syncthreads();
    if (tid < 32) {
        float pt = 0.f, ht = 0.f;
#pragma unroll
        for (int g2 = 0; g2 < 8; g2++) { pt += sp[g2*32 + tid]; ht += sh[g2*32 + tid]; }
        g_probs[n] = pt;
        g_ph[n] = ht * (1.f/1024.f);
    }
}

__global__ void k_ptot() {
    __shared__ float red[1024];
    int t = threadIdx.x;
    red[t] = g_probs[t] + g_probs[t + 1024];
    __syncthreads();
    for (int st = 512; st > 0; st >>= 1) {
        if (t < st) red[t] += red[t + st];
        __syncthreads();
    }
    if (t == 0) g_ptot = red[0];
}

__global__ void k_inject(const float* __restrict__ src, float* __restrict__ dst) {
    int i = blockIdx.x, d = threadIdx.x;      // 512 threads
    float inv = 1.f / (g_ptot + 1e-8f);
    float p = g_probs[i] * inv;
    float interf = 0.f;
#pragma unroll
    for (int k = 0; k < 6; k++) interf += p - g_probs[i ^ (1 << k)] * inv;
    interf *= 0.03f;
    float phc = g_ph[i] * 0.3f;
    float c = cosf(phc), s = sinf(phc);
    float scale = 0.8f + 0.4f * p;
    float t1 = src[i*DD + d]       * scale;
    float t2 = src[i*DD + HD2 + d] * scale;
    dst[i*DD + d]       = 0.5f*(t1*c - t2*s) + 0.5f*t1 + interf;
    dst[i*DD + HD2 + d] = 0.5f*(t1*s + t2*c) + 0.5f*t2 + interf;
}

// smem-resident per-column frustration recurrence; 8 blocks x 128 columns
__global__ void k_frust(const float* __restrict__ fs) {
    extern __shared__ float fsm[];                 // sc[128*128] + sfs[1024]
    float* sc  = fsm;
    float* sfs = fsm + 128*128;
    int t = threadIdx.x;
    int col = blockIdx.x * 128 + t;
    for (int r = 0; r < 128; r++) sc[r*128 + t] = g_cells[r*DD + col];
    for (int i = t; i < 1024; i += 128) sfs[i] = fs[i];
    __syncthreads();
    float p0 = g_cells[128*DD + col];
    float p1 = g_cells[256*DD + col];
    float p2 = g_cells[512*DD + col];
    for (int i = 0; i < 128; i++) {
        float n0=0.f, n1=0.f, n2=0.f;
        if (i + 1 < 128) {
            n0 = g_cells[((i+1)^128)*DD + col];
            n1 = g_cells[((i+1)^256)*DD + col];
            n2 = g_cells[((i+1)^512)*DD + col];
        }
        float fi = sfs[i];
        float infl = fi*(sfs[i^128]*p0 + sfs[i^256]*p1 + sfs[i^512]*p2);
#pragma unroll
        for (int b = 0; b < 7; b++) {
            int j = i ^ (1 << b);
            infl += fi * sfs[j] * sc[j*128 + t];
        }
        sc[i*128 + t] = 0.85f * sc[i*128 + t] + 0.015f * infl;
        p0 = n0; p1 = n1; p2 = n2;
    }
    for (int r = 0; r < 128; r++) g_cells[r*DD + col] = sc[r*128 + t];
}

// morph: wave factor applied at load (runs only when step%3==0); writes
// post-wave values so downstream must not re-apply wf to rows < 48.
__global__ void k_morph(const int* __restrict__ step) {
    if (step[0] % 3 != 0) return;
    __shared__ float sv[8*48];
    int t = threadIdx.x;
    int lc = t >> 3, kt = t & 7;
    int col = blockIdx.x * 8 + lc;
    for (int k = kt; k < 48; k += 8)
        sv[lc*48 + k] = __fmul_rn(g_cells[k*DD + col], g_wavef[k]);
    __syncwarp();
    for (int i = 0; i < 48; i++) {
        float vi = sv[lc*48 + i];
        float s = 0.f;
#pragma unroll
        for (int j = 0; j < 6; j++) s += tanhf(sv[lc*48 + kt*6 + j] - vi);
        s += __shfl_down_sync(0xffffffffu, s, 4, 8);
        s += __shfl_down_sync(0xffffffffu, s, 2, 8);
        s += __shfl_down_sync(0xffffffffu, s, 1, 8);
        if (kt == 0) sv[lc*48 + i] = 0.9f * vi + 0.1f * s * (1.f/47.f);
        __syncwarp();
    }
    for (int k = kt; k < 48; k += 8) g_cells[k*DD + col] = sv[lc*48 + k];
}

__global__ void k_fmean(const int* __restrict__ step) {
    int f = blockIdx.x;
    int col = blockIdx.y * 128 + threadIdx.x;
    bool m = (step[0] % 3 == 0);
    float s = 0.f;
    for (int r = 0; r < 256; r++) {
        int row = f*256 + r;
        float wf = (m && row < 48) ? 1.f : g_wavef[row];
        s += __fmul_rn(g_cells[(size_t)row*DD + col], wf);
    }
    g_fmean[f*DD + col] = s * (1.f/256.f);
}

// faction fused with bcast; wave factor applied inline; writes cellsB + cellsR
__global__ void k_faction(const int* __restrict__ step) {
    int n = blockIdx.x;
    int f = n >> 8, r = n & 255;
    bool m = (step[0] % 3 == 0);
    bool debate = (step[0] > 5) && (r < 64);
    float wf = (m && n < 48) ? 1.f : g_wavef[n];
#pragma unroll
    for (int q = 0; q < 4; q++) {
        int col = q * 256 + threadIdx.x;
        float cw = __fmul_rn(g_cells[n*DD + col], wf);
        float v = 0.85f * cw + 0.15f * g_fmean[f*DD + col];
        if (debate) {
            float g = 0.f;
#pragma unroll
            for (int ff = 0; ff < 8; ff++) g += g_fmean[ff*DD + col];
            v = 0.85f * v + 0.15f * (g * 0.125f);
        }
        float v0 = v + 0.1f * g_xproj[col];
        float v1 = v + 0.1f * g_xproj[DD + col];
        g_cellsB[(size_t)n*DD + col]        = v0;
        g_cellsB[(size_t)(NC + n)*DD + col] = v1;
        g_cellsR[(size_t)n*DD + col]        = tfr(v0);
        g_cellsR[(size_t)(NC + n)*DD + col] = tfr(v1);
    }
}

__global__ void k_xproj(const float* __restrict__ x, const float* __restrict__ w,
                        const float* __restrict__ b) {
    int gw   = (blockIdx.x * blockDim.x + threadIdx.x) >> 5;
    int lane = threadIdx.x & 31;
    if (gw >= BB * DD) return;
    int bi = gw / DD, j = gw % DD;
    const float* xr = x + bi * INDIM;
    const float* wr = w + (size_t)j * INDIM;
    float s = 0.f;
    for (int k = lane; k < INDIM; k += 32) s += xr[k] * wr[k];
    for (int o = 16; o > 0; o >>= 1) s += __shfl_down_sync(0xffffffffu, s, o);
    if (lane == 0) g_xproj[gw] = s + b[j];
}

// ------------------------- tf32 tensor-core GEMMs -------------------------
__device__ __forceinline__ void mma8(float* c, const uint32_t* a, const uint32_t* b) {
    asm volatile(
        "mma.sync.aligned.m16n8k8.row.col.f32.tf32.tf32.f32 "
        "{%0,%1,%2,%3},{%4,%5,%6,%7},{%8,%9},{%0,%1,%2,%3};"
        : "+f"(c[0]), "+f"(c[1]), "+f"(c[2]), "+f"(c[3])
        : "r"(a[0]), "r"(a[1]), "r"(a[2]), "r"(a[3]), "r"(b[0]), "r"(b[1]));
}
__device__ __forceinline__ void cpa16(float* dst, const float* src) {
    unsigned d = (unsigned)__cvta_generic_to_shared(dst);
    asm volatile("cp.async.cg.shared.global [%0], [%1], 16;\n" :: "r"(d), "l"(src));
}
__device__ __forceinline__ void cp_commit() { asm volatile("cp.async.commit_group;\n"); }
__device__ __forceinline__ void cp_wait0() { asm volatile("cp.async.wait_group 0;\n"); }

template<bool DOC>
__device__ __forceinline__ uint32_t opnd(float x) {
    return DOC ? f2tf32(x) : __float_as_uint(x);
}

#define AST 40           // smem row stride (floats) for [row][k] tiles
#define BSTN 132         // smem row stride for [k][n] tiles (NN B)
#define NT_STAGE (128*AST*2)
#define NN_STAGE (128*AST + 32*BSTN)

#define LOAD_AFRAG(AS, AF, KC, DOC)                                       \
    _Pragma("unroll")                                                     \
    for (int mt = 0; mt < 4; mt++) {                                      \
        int rb = wm*64 + mt*16 + g;                                       \
        float2 lo = *(const float2*)&(AS)[rb*AST + (KC)];                 \
        float2 hi = *(const float2*)&(AS)[(rb+8)*AST + (KC)];             \
        (AF)[mt][0] = opnd<DOC>(lo.x); (AF)[mt][2] = opnd<DOC>(lo.y);     \
        (AF)[mt][1] = opnd<DOC>(hi.x); (AF)[mt][3] = opnd<DOC>(hi.y);     \
    }

// C = alpha*A@W^T (+bias); EXPO: C = tf32(exp(alpha*acc)); RO: round output.
template<bool CA, bool CB, bool EXPO, bool RO>
__global__ void __launch_bounds__(256, 2) tgemm_nt(
    const float* __restrict__ A, int lda, long soA, long siA,
    const float* __restrict__ W, int ldw, long soW, long siW,
    const float* __restrict__ bias,
    float* __restrict__ C, int ldc, long soC, long siC,
    int inner, int K, float alpha)
{
    extern __shared__ float sm[];
    int z = blockIdx.z;
    int zo = z / inner, zi = z - zo * inner;
    A += (size_t)zo*soA + (size_t)zi*siA;
    W += (size_t)zo*soW + (size_t)zi*siW;
    C += (size_t)zo*soC + (size_t)zi*siC;

    int tid  = threadIdx.x;
    int wid  = tid >> 5, lane = tid & 31;
    int g = lane >> 2, t = lane & 3;
    int wm = wid & 1, wn = wid >> 1;

    int lr = tid >> 3;
    int lc = (tid & 7) << 2;
    const float* Ab = A + (size_t)(blockIdx.y*128 + lr)*lda + lc;
    const float* Wb = W + (size_t)(blockIdx.x*128 + lr)*ldw + lc;

    float acc[4][4][4] = {};
    int KT = K >> 5;

#define NT_LOAD(KT_)                                                      \
    {                                                                     \
        float* a_s = sm + ((KT_)&1)*NT_STAGE;                             \
        float* b_s = a_s + 128*AST;                                       \
        _Pragma("unroll")                                                 \
        for (int i = 0; i < 4; i++) {                                     \
            cpa16(&a_s[(lr + 32*i)*AST + lc], Ab + (size_t)(32*i)*lda + (KT_)*32); \
            cpa16(&b_s[(lr + 32*i)*AST + lc], Wb + (size_t)(32*i)*ldw + (KT_)*32); \
        }                                                                 \
        cp_commit();                                                      \
    }

    NT_LOAD(0);

    for (int kt = 0; kt < KT; kt++) {
        cp_wait0();
        __syncthreads();
        if (kt + 1 < KT) NT_LOAD(kt+1);
        const float* a_s = sm + (kt&1)*NT_STAGE;
        const float* b_s = a_s + 128*AST;
#pragma unroll
        for (int ks = 0; ks < 4; ks++) {
            uint32_t af[4][4], bf[4][2];
            int kc = ks*8 + 2*t;
            LOAD_AFRAG(a_s, af, kc, CA)
#pragma unroll
            for (int nt = 0; nt < 4; nt++) {
                int nb = wn*32 + nt*8 + g;
                float2 bb = *(const float2*)&b_s[nb*AST + kc];
                bf[nt][0] = opnd<CB>(bb.x); bf[nt][1] = opnd<CB>(bb.y);
            }
#pragma unroll
            for (int mt = 0; mt < 4; mt++)
#pragma unroll
                for (int nt = 0; nt < 4; nt++)
                    mma8(acc[mt][nt], af[mt], bf[nt]);
        }
    }

    int row0 = blockIdx.y*128 + wm*64 + g;
    int col0 = blockIdx.x*128 + wn*32 + 2*t;
#pragma unroll
    for (int nt = 0; nt < 4; nt++) {
        int c = col0 + nt*8;
        float2 bv = make_float2(0.f, 0.f);
        if (bias) bv = *(const float2*)&bias[c];
#pragma unroll
        for (int mt = 0; mt < 4; mt++) {
            int r = row0 + mt*16;
            float2 o0, o1;
            if (EXPO) {
                o0.x = tfr(__expf(alpha*acc[mt][nt][0]));
                o0.y = tfr(__expf(alpha*acc[mt][nt][1]));
                o1.x = tfr(__expf(alpha*acc[mt][nt][2]));
                o1.y = tfr(__expf(alpha*acc[mt][nt][3]));
            } else {
                o0.x = alpha*acc[mt][nt][0] + bv.x;  o0.y = alpha*acc[mt][nt][1] + bv.y;
                o1.x = alpha*acc[mt][nt][2] + bv.x;  o1.y = alpha*acc[mt][nt][3] + bv.y;
                if (RO) {
                    o0.x = tfr(o0.x); o0.y = tfr(o0.y);
                    o1.x = tfr(o1.x); o1.y = tfr(o1.y);
                }
            }
            *(float2*)&C[(size_t)r*ldc + c]     = o0;
            *(float2*)&C[(size_t)(r+8)*ldc + c] = o1;
        }
    }
}

// C = A@B, batched. ZC: per-row Z = sum_k A (from smem), scale rows by 1/Z,
// write Z to Zout. RO: round output. Requires grid.x == 1 when ZC.
template<bool CA, bool CB, bool RO, bool ZC>
__global__ void __launch_bounds__(256, 2) tgemm_nn(
    const float* __restrict__ A, int lda, long soA, long siA,
    const float* __restrict__ Bm, int ldb, long soB, long siB,
    float* __restrict__ Zout,
    float* __restrict__ C, int ldc, long soC, long siC,
    int inner, int K)
{
    extern __shared__ float sm[];
    __shared__ float zs[256];
    __shared__ float zfin[128];
    int z = blockIdx.z;
    int zo = z / inner, zi = z - zo * inner;
    A  += (size_t)zo*soA + (size_t)zi*siA;
    Bm += (size_t)zo*soB + (size_t)zi*siB;
    C  += (size_t)zo*soC + (size_t)zi*siC;

    int tid  = threadIdx.x;
    int wid  = tid >> 5, lane = tid & 31;
    int g = lane >> 2, t = lane & 3;
    int wm = wid & 1, wn = wid >> 1;

    int lr = tid >> 3;
    int lc = (tid & 7) << 2;
    const float* Ab = A + (size_t)(blockIdx.y*128 + lr)*lda + lc;
    int br = tid >> 5;
    int bc = (tid & 31) << 2;
    const float* Bb = Bm + blockIdx.x*128 + bc;

    float acc[4][4][4] = {};
    float zacc = 0.f;
    int zr = tid & 127, zh = tid >> 7;
    int KT = K >> 5;

#define NN_LOAD(KT_)                                                      \
    {                                                                     \
        float* a_s = sm + ((KT_)&1)*NN_STAGE;                             \
        float* b_s = a_s + 128*AST;                                       \
        _Pragma("unroll")                                                 \
        for (int i = 0; i < 4; i++) {                                     \
            cpa16(&a_s[(lr + 32*i)*AST + lc], Ab + (size_t)(32*i)*lda + (KT_)*32); \
            cpa16(&b_s[(br + 8*i)*BSTN + bc], Bb + (size_t)((KT_)*32 + br + 8*i)*ldb); \
        }                                                                 \
        cp_commit();                                                      \
    }

    NN_LOAD(0);

    for (int kt = 0; kt < KT; kt++) {
        cp_wait0();
        __syncthreads();
        if (kt + 1 < KT) NN_LOAD(kt+1);
        const float* a_s = sm + (kt&1)*NN_STAGE;
        const float* b_s = a_s + 128*AST;
#pragma unroll
        for (int ks = 0; ks < 4; ks++) {
            uint32_t af[4][4], bf[4][2];
            int kc = ks*8 + 2*t;
            LOAD_AFRAG(a_s, af, kc, CA)
#pragma unroll
            for (int nt = 0; nt < 4; nt++) {
                int nb = wn*32 + nt*8 + g;
                bf[nt][0] = opnd<CB>(b_s[kc*BSTN + nb]);
                bf[nt][1] = opnd<CB>(b_s[(kc+1)*BSTN + nb]);
            }
#pragma unroll
            for (int mt = 0; mt < 4; mt++)
#pragma unroll
                for (int nt = 0; nt < 4; nt++)
                    mma8(acc[mt][nt], af[mt], bf[nt]);
        }
        if (ZC) {
            const float* ap = a_s + zr*AST + zh*16;
#pragma unroll
            for (int j = 0; j < 4; j++) {
                float4 v = *(const float4*)(ap + j*4);
                zacc += v.x + v.y + v.z + v.w;
            }
        }
    }

    if (ZC) {
        zs[tid] = zacc;
        __syncthreads();
        if (tid < 128) {
            float zv = zs[tid] + zs[tid + 128];
            zfin[tid] = 1.f / zv;
            Zout[(size_t)blockIdx.z*NC + blockIdx.y*128 + tid] = zv;
        }
        __syncthreads();
    }

    int row0 = blockIdx.y*128 + wm*64 + g;
    int col0 = blockIdx.x*128 + wn*32 + 2*t;
    float zi0[4], zi1[4];
    if (ZC) {
#pragma unroll
        for (int mt = 0; mt < 4; mt++) {
            zi0[mt] = zfin[wm*64 + mt*16 + g];
            zi1[mt] = zfin[wm*64 + mt*16 + g + 8];
        }
    }
#pragma unroll
    for (int nt = 0; nt < 4; nt++) {
        int c = col0 + nt*8;
#pragma unroll
        for (int mt = 0; mt < 4; mt++) {
            int r = row0 + mt*16;
            float o0 = acc[mt][nt][0], o1 = acc[mt][nt][1];
            float o2 = acc[mt][nt][2], o3 = acc[mt][nt][3];
            if (ZC) { o0 *= zi0[mt]; o1 *= zi0[mt]; o2 *= zi1[mt]; o3 *= zi1[mt]; }
            if (RO) { o0 = tfr(o0); o1 = tfr(o1); o2 = tfr(o2); o3 = tfr(o3); }
            *(float2*)&C[(size_t)r*ldc + c]     = make_float2(o0, o1);
            *(float2*)&C[(size_t)(r+8)*ldc + c] = make_float2(o2, o3);
        }
    }
}

// --------- tension partials: single pass over e, Z from g_rowsum ----------
__global__ void __launch_bounds__(256) k_tens(const float* __restrict__ E) {
    __shared__ float r1[256], r2[256];
    __shared__ float zinv[8];
    int q = blockIdx.x, b = blockIdx.y;
    int tid = threadIdx.x;
    if (tid < 8) zinv[tid] = 0.125f / g_rowsum[(b*8 + tid)*NC + q];
    __syncthreads();
    const float* base = E + (size_t)b*8*NC*NC + (size_t)q*NC;
    const float mu0 = 1.f / 2048.f;
    float zv[8];
#pragma unroll
    for (int h = 0; h < 8; h++) zv[h] = zinv[h];
    float s1 = 0.f, s2 = 0.f;
    for (int k = tid; k < 2048; k += 256) {
        float m = 0.f;
#pragma unroll
        for (int h = 0; h < 8; h++) m += __ldg(&base[(size_t)h*NC*NC + k]) * zv[h];
        s1 += m;
        float d = m - mu0;
        s2 += d * d;
    }
    r1[tid] = s1; r2[tid] = s2; __syncthreads();
    for (int st = 128; st > 0; st >>= 1) {
        if (tid < st) { r1[tid] += r1[tid+st]; r2[tid] += r2[tid+st]; }
        __syncthreads();
    }
    if (tid == 0) { int bq = b*2048 + q; g_part1[bq] = r1[0]; g_part2[bq] = r2[0]; }
}

// outp != nullptr on the final layer: writes tension scalar directly.
__global__ void k_tred(float* outp) {
    __shared__ float r1[1024], r2[1024];
    int t = threadIdx.x;
    float s1 = 0.f, s2 = 0.f;
    for (int i = t; i < BB*NC; i += 1024) { s1 += g_part1[i]; s2 += g_part2[i]; }
    r1[t] = s1; r2[t] = s2; __syncthreads();
    for (int st = 512; st > 0; st >>= 1) {
        if (t < st) { r1[t] += r1[t+st]; r2[t] += r2[t+st]; }
        __syncthreads();
    }
    if (t == 0) {
        double Ne = 8388608.0;
        double S1 = (double)r1[0], D2 = (double)r2[0];
        double mu0 = 1.0 / 2048.0;
        double mu  = S1 / Ne;
        double var = (D2 - Ne * (mu - mu0) * (mu - mu0)) / (Ne - 1.0);
        if (var < 0.0) var = 0.0;
        g_tension += (float)sqrt(var);
        if (outp) outp[0] = g_tension * 0.5f;
    }
}

// addln also writes tf32-rounded copy for the next GEMM's A operand
__global__ void k_addln(const float* __restrict__ g, const float* __restrict__ bta) {
    __shared__ float red[256];
    size_t row = blockIdx.x;
    int t = threadIdx.x;
    float v[4];
    float s = 0.f;
#pragma unroll
    for (int q = 0; q < 4; q++) {
        int d = q * 256 + t;
        v[q] = g_cellsB[row*DD + d] + g_tmp[row*DD + d];
        s += v[q];
    }
    red[t] = s; __syncthreads();
    for (int st = 128; st > 0; st >>= 1) {
        if (t < st) red[t] += red[t + st];
        __syncthreads();
    }
    float mu = red[0] * (1.f/1024.f);
    __syncthreads();
    float s2 = 0.f;
#pragma unroll
    for (int q = 0; q < 4; q++) { float d = v[q] - mu; s2 += d * d; }
    red[t] = s2; __syncthreads();
    for (int st = 128; st > 0; st >>= 1) {
        if (t < st) red[t] += red[t + st];
        __syncthreads();
    }
    float var  = red[0] * (1.f/1024.f);
    float rstd = rsqrtf(var + 1e-5f);
#pragma unroll
    for (int q = 0; q < 4; q++) {
        int d = q * 256 + t;
        float o = (v[q] - mu) * rstd * g[d] + bta[d];
        g_cellsB[row*DD + d] = o;
        g_cellsR[row*DD + d] = tfr(o);
    }
}

// ------------------------------- host launch -------------------------------
extern "C" void kernel_launch(void* const* d_in, const int* in_sizes, int n_in,
                              void* d_out, int out_size) {
    const float* x           = (const float*)d_in[0];
    const float* amp_real    = (const float*)d_in[1];
    const float* amp_imag    = (const float*)d_in[2];
    const float* coin_real   = (const float*)d_in[3];
    const float* coin_imag   = (const float*)d_in[4];
    const float* cell_emb    = (const float*)d_in[5];
    const float* fsigns      = (const float*)d_in[6];
    const float* w_in        = (const float*)d_in[7];
    const float* b_in        = (const float*)d_in[8];
    const float* attn_in_w   = (const float*)d_in[9];
    const float* attn_in_b   = (const float*)d_in[10];
    const float* attn_out_w  = (const float*)d_in[11];
    const float* attn_out_b  = (const float*)d_in[12];
    const float* ln_g        = (const float*)d_in[13];
    const float* ln_b        = (const float*)d_in[14];
    const float* w_out       = (const float*)d_in[15];
    const float* b_out       = (const float*)d_in[16];
    const int*   step        = (const int*)d_in[17];
    float* out = (float*)d_out;

    float *p_ar0, *p_ai0, *p_ar1, *p_ai1, *p_cells, *p_cellsB, *p_cellsR,
          *p_qkv, *p_scores, *p_av, *p_tmp, *p_wqkv, *p_wout, *p_wfin, *p_rowsum;
    cudaGetSymbolAddress((void**)&p_ar0,    g_ampr0);
    cudaGetSymbolAddress((void**)&p_ai0,    g_ampi0);
    cudaGetSymbolAddress((void**)&p_ar1,    g_ampr1);
    cudaGetSymbolAddress((void**)&p_ai1,    g_ampi1);
    cudaGetSymbolAddress((void**)&p_cells,  g_cells);
    cudaGetSymbolAddress((void**)&p_cellsB, g_cellsB);
    cudaGetSymbolAddress((void**)&p_cellsR, g_cellsR);
    cudaGetSymbolAddress((void**)&p_qkv,    g_qkv);
    cudaGetSymbolAddress((void**)&p_scores, g_scores);
    cudaGetSymbolAddress((void**)&p_av,     g_av);
    cudaGetSymbolAddress((void**)&p_tmp,    g_tmp);
    cudaGetSymbolAddress((void**)&p_wqkv,   g_wqkv);
    cudaGetSymbolAddress((void**)&p_wout,   g_wout);
    cudaGetSymbolAddress((void**)&p_wfin,   g_wfin);
    cudaGetSymbolAddress((void**)&p_rowsum, g_rowsum);

    const int nt_smem = NT_STAGE*2*(int)sizeof(float);  // 81920
    const int nn_smem = NN_STAGE*2*(int)sizeof(float);  // 74752
    const int fr_smem = (128*128 + 1024)*(int)sizeof(float); // 69632
    const int ww_smem = 32768*(int)sizeof(float);       // 131072 (dbl-buffered)

    static cudaStream_t sB;
    static cudaEvent_t evF, evB, evA0, evA1, evT0, evT1;
    static int init_done = 0;
    if (!init_done) {
        cudaFuncSetAttribute(tgemm_nt<false,false,false,true>,  cudaFuncAttributeMaxDynamicSharedMemorySize, nt_smem);
        cudaFuncSetAttribute(tgemm_nt<false,false,true,false>,  cudaFuncAttributeMaxDynamicSharedMemorySize, nt_smem);
        cudaFuncSetAttribute(tgemm_nt<false,false,false,false>, cudaFuncAttributeMaxDynamicSharedMemorySize, nt_smem);
        cudaFuncSetAttribute(tgemm_nn<false,false,true,true>,   cudaFuncAttributeMaxDynamicSharedMemorySize, nn_smem);
        cudaFuncSetAttribute(k_frust,  cudaFuncAttributeMaxDynamicSharedMemorySize, fr_smem);
        cudaFuncSetAttribute(k_walk2,  cudaFuncAttributeMaxDynamicSharedMemorySize, ww_smem);
        cudaStreamCreateWithFlags(&sB, cudaStreamNonBlocking);
        cudaEventCreateWithFlags(&evF,  cudaEventDisableTiming);
        cudaEventCreateWithFlags(&evB,  cudaEventDisableTiming);
        cudaEventCreateWithFlags(&evA0, cudaEventDisableTiming);
        cudaEventCreateWithFlags(&evA1, cudaEventDisableTiming);
        cudaEventCreateWithFlags(&evT0, cudaEventDisableTiming);
        cudaEventCreateWithFlags(&evT1, cudaEventDisableTiming);
        init_done = 1;
    }
    cudaEvent_t evA[2] = {evA0, evA1};
    cudaEvent_t evT[2] = {evT0, evT1};

    // ---- fork side stream: weight round-copy + xproj (independent of preamble)
    cudaEventRecord(evF, 0);
    cudaStreamWaitEvent(sB, evF, 0);
    {
        int n4a = 2*D3*DD/4, n4b = 2*DD*DD/4, n4c = INDIM*DD/4;
        k_roundcpy<<<(n4a+255)/256, 256, 0, sB>>>(p_wqkv, attn_in_w, n4a);
        k_roundcpy<<<(n4b+255)/256, 256, 0, sB>>>(p_wout, attn_out_w, n4b);
        k_roundcpy<<<(n4c+255)/256, 256, 0, sB>>>(p_wfin, w_out, n4c);
        k_xproj<<<256, 256, 0, sB>>>(x, w_in, b_in);
    }
    cudaEventRecord(evB, sB);

    // ---- update_cells preamble (main stream, serial) ----
    k_xmean<<<1, 256>>>(x, BB * INDIM);
    k_wavef<<<2, 1024>>>(step);

    // fused double walk: both passes' partials, no amp DRAM round-trip
    k_walk2<<<512, 256, ww_smem>>>(amp_real, amp_imag, coin_real, coin_imag,
                                   p_ar1, p_ai1, p_ar0, p_ai0);
    k_pred<<<64, 256>>>(p_ar1, p_ai1);
    k_ptot<<<1, 1024>>>();
    k_inject<<<NC, 512>>>(cell_emb, p_cells);
    k_pred<<<64, 256>>>(p_ar0, p_ai0);
    k_ptot<<<1, 1024>>>();
    k_inject<<<NC, 512>>>(p_cells, p_cells);

    k_frust<<<8, 128, fr_smem>>>(fsigns);
    k_morph<<<128, 64>>>(step);
    k_fmean<<<dim3(8, 8), 128>>>(step);

    // join: faction (fused with bcast + wave) needs xproj + wqkv ready
    cudaStreamWaitEvent(0, evB, 0);
    k_faction<<<NC, 256>>>(step);

    float* tens_out = (out_size >= BB*NC*INDIM + 1) ? (out + (size_t)BB*NC*INDIM)
                                                    : (float*)nullptr;

    const float inv_sqrt_hd = 0.0883883476483184f; // 1/sqrt(128)
    for (int l = 0; l < 2; l++) {
        // qkv = cellsR @ Wqkv^T + b : zero-cvt inner loop (A pre-rounded)
        tgemm_nt<false,false,false,true><<<dim3(24, 32, 1), 256, nt_smem>>>(
            p_cellsR, DD, 0, 0,
            p_wqkv + (size_t)l*D3*DD, DD, 0, 0,
            attn_in_b + (size_t)l*D3,
            p_qkv, D3, 0, 0, 1, DD, 1.f);

        // scores -> raw e: layer 2 must wait for layer-1 k_tens (reads g_scores)
        if (l == 1) cudaStreamWaitEvent(0, evT[0], 0);
        tgemm_nt<false,false,true,false><<<dim3(16, 16, 16), 256, nt_smem>>>(
            p_qkv,        D3, (long)NC*D3, 128,
            p_qkv + 1024, D3, (long)NC*D3, 128,
            nullptr,
            p_scores, NC, (long)8*NC*NC, (long)NC*NC,
            8, HDIM, inv_sqrt_hd);

        // av = (e @ V) / Z : Z computed in-kernel; Z -> g_rowsum
        tgemm_nn<false,false,true,true><<<dim3(1, 16, 16), 256, nn_smem>>>(
            p_scores,     NC, (long)8*NC*NC, (long)NC*NC,
            p_qkv + 2048, D3, (long)NC*D3, 128,
            p_rowsum,
            p_av, DD, (long)NC*DD, 128,
            8, NC);

        // tension partials overlap with out-proj/addln/next-qkv on side stream
        cudaEventRecord(evA[l], 0);
        cudaStreamWaitEvent(sB, evA[l], 0);
        k_tens<<<dim3(NC, BB), 256, 0, sB>>>(p_scores);
        k_tred<<<1, 1024, 0, sB>>>(l == 1 ? tens_out : (float*)nullptr);
        cudaEventRecord(evT[l], sB);

        // out-proj: both operands pre-rounded; output exact (residual)
        tgemm_nt<false,false,false,false><<<dim3(8, 32, 1), 256, nt_smem>>>(
            p_av, DD, 0, 0,
            p_wout + (size_t)l*DD*DD, DD, 0, 0,
            attn_out_b + (size_t)l*DD,
            p_tmp, DD, 0, 0, 1, DD, 1.f);

        k_addln<<<BB*NC, 256>>>(ln_g + (size_t)l*DD, ln_b + (size_t)l*DD);
    }

    // final projection: zero-cvt (A pre-rounded via cellsR, B pre-rounded)
    tgemm_nt<false,false,false,false><<<dim3(4, 32, 1), 256, nt_smem>>>(
        p_cellsR, DD, 0, 0,
        p_wfin, DD, 0, 0,
        b_out,
        out, INDIM, 0, 0, 1, DD, 1.f);

    // join side stream back into the capture-origin stream
    cudaStreamWaitEvent(0, evT[1], 0);
}

// round 17
// speedup vs baseline: 1.0048x; 1.0048x over previous
#include <cuda_runtime.h>
#include <math.h>
#include <stdint.h>

#define NC    2048
#define DD    1024
#define HD2   512
#define BB    2
#define HH    8
#define HDIM  128
#define D3    3072
#define INDIM 512

// ----------------------------- device scratch -----------------------------
__device__ float g_ampr0[NC*2*DD];   // reused: walk prob partials (pass 2)
__device__ float g_ampi0[NC*2*DD];   // reused: walk phase partials (pass 2)
__device__ float g_ampr1[NC*2*DD];   // reused: walk prob partials (pass 1)
__device__ float g_ampi1[NC*2*DD];   // reused: walk phase partials (pass 1)
__device__ float g_probs[NC];
__device__ float g_ph[NC];
__device__ float g_probs2[NC];
__device__ float g_ph2[NC];
__device__ float g_wavef[NC];
__device__ float g_cells[NC*DD];
__device__ float g_fmean[8*DD];
__device__ float g_xproj[BB*DD];
__device__ float g_cellsB[BB*NC*DD];
__device__ float g_cellsR[BB*NC*DD];  // tf32-rounded cellsB (GEMM A operand)
__device__ float g_qkv[(size_t)BB*NC*D3];
__device__ float g_scores[(size_t)BB*HH*NC*NC];   // raw exp(S), 256 MiB
__device__ float g_rowsum[BB*HH*NC];
__device__ float g_av[(size_t)BB*NC*DD];
__device__ float g_tmp[(size_t)BB*NC*DD];
__device__ float g_part1[BB*NC];
__device__ float g_part2[BB*NC];
__device__ float g_wqkv[2*D3*DD];     // tf32-rounded attn_in_w
__device__ float g_wout[2*DD*DD];     // tf32-rounded attn_out_w
__device__ float g_wfin[INDIM*DD];    // tf32-rounded w_out
__device__ float g_xmean;
__device__ float g_ptot;
__device__ float g_ptot2;
__device__ float g_tension;

// ----------------------------- small kernels ------------------------------
__global__ void k_xmean(const float* __restrict__ x, int n) {
    __shared__ float red[256];
    float s = 0.f;
    for (int i = threadIdx.x; i < n; i += 256) s += x[i];
    red[threadIdx.x] = s; __syncthreads();
    for (int st = 128; st > 0; st >>= 1) {
        if (threadIdx.x < st) red[threadIdx.x] += red[threadIdx.x + st];
        __syncthreads();
    }
    if (threadIdx.x == 0) { g_xmean = red[0] / (float)n; g_tension = 0.f; }
}

__device__ __forceinline__ uint32_t f2tf32(float x) {
    uint32_t r; asm("cvt.rna.tf32.f32 %0, %1;" : "=r"(r) : "f"(x)); return r;
}
__device__ __forceinline__ float tfr(float x) { return __uint_as_float(f2tf32(x)); }

// round-copy weights to tf32 (idempotent w.r.t. in-GEMM cvt)
__global__ void k_roundcpy(float* __restrict__ dst, const float* __restrict__ src, int n4) {
    int i = blockIdx.x * 256 + threadIdx.x;
    if (i < n4) {
        float4 v = ((const float4*)src)[i];
        v.x = tfr(v.x); v.y = tfr(v.y); v.z = tfr(v.z); v.w = tfr(v.w);
        ((float4*)dst)[i] = v;
    }
}

// standing-wave factor table (replaces 16MB cells read-modify-write)
__global__ void k_wavef(const int* __restrict__ step) {
    int i = blockIdx.x*1024 + threadIdx.x;
    float st  = (float)step[0];
    float fwd = fmodf(st * 0.15f, 2048.f);
    float bwd = fmodf(2048.f - st * 0.15f, 2048.f);
    float fi  = (float)i;
    float c1 = coshf((fi - fwd) * 0.5f), c2 = coshf((fi - bwd) * 0.5f);
    g_wavef[i] = 1.f + 0.03f * (1.f/(c1*c1) + 1.f/(c2*c2));
}

// ---- fused double quantum-walk: 512 blocks x 2 columns, dbl-buffered smem --
template<bool RC>
__device__ __forceinline__ void walk_pass(
    const float* __restrict__ sr0, const float* __restrict__ si0,
    const float* __restrict__ sr1, const float* __restrict__ si1,
    float* __restrict__ dr0, float* __restrict__ di0,
    float* __restrict__ dr1, float* __restrict__ di1,
    float c00r, float c00i, float c01r, float c01i,
    float c10r, float c10i, float c11r, float c11i,
    float pc, float ps, int c, int nl, int blk,
    float* __restrict__ pp, float* __restrict__ hp, bool dowrite)
{
    for (int it = 0; it < 16; it++) {
        int n = nl + 128*it;
        int base = n*2 + c;
        float a0r = sr0[base], a0i = si0[base], a1r = sr1[base], a1i = si1[base];
        float n0r, n0i, sr, si;
        if (RC) {
            n0r = c00r*a0r + c01r*a1r;
            n0i = c00r*a0i + c01r*a1i;
            sr = 0.f; si = 0.f;
#pragma unroll
            for (int j = 0; j < 11; j++) {
                int mb = (n ^ (1<<j))*2 + c;
                sr += c10r*sr0[mb] + c11r*sr1[mb];
                si += c10r*si0[mb] + c11r*si1[mb];
            }
        } else {
            n0r = c00r*a0r - c00i*a0i + c01r*a1r - c01i*a1i;
            n0i = c00r*a0i + c00i*a0r + c01r*a1i + c01i*a1r;
            sr = 0.f; si = 0.f;
#pragma unroll
            for (int j = 0; j < 11; j++) {
                int mb = (n ^ (1<<j))*2 + c;
                float x0r = sr0[mb], x0i = si0[mb], x1r = sr1[mb], x1i = si1[mb];
                sr += c10r*x0r - c10i*x0i + c11r*x1r - c11i*x1i;
                si += c10r*x0i + c10i*x0r + c11r*x1i + c11i*x1r;
            }
        }
        float n1r = sr*(1.f/11.f), n1i = si*(1.f/11.f);
        float o0r = n0r*pc - n0i*ps, o0i = n0r*ps + n0i*pc;
        float o1r = n1r*pc - n1i*ps, o1i = n1r*ps + n1i*pc;
        if (dowrite) {
            dr0[base] = o0r; di0[base] = o0i;
            dr1[base] = o1r; di1[base] = o1i;
        }
        float pq = o0r*o0r + o0i*o0i + o1r*o1r + o1i*o1i;
        float hq = atan2f(o0i + o1i, o0r + o1r);
        pq += __shfl_down_sync(0xffffffffu, pq, 1, 2);
        hq += __shfl_down_sync(0xffffffffu, hq, 1, 2);
        if (c == 0) { pp[blk*2048 + n] = pq; hp[blk*2048 + n] = hq; }
    }
}

__global__ void __launch_bounds__(256, 1) k_walk2(
    const float* __restrict__ inr, const float* __restrict__ ini,
    const float* __restrict__ cr, const float* __restrict__ ci,
    float* __restrict__ pp1, float* __restrict__ hp1,
    float* __restrict__ pp2, float* __restrict__ hp2)
{
    extern __shared__ float ws[];
    float* A0r = ws;            float* A0i = ws + 4096;
    float* A1r = ws + 8192;     float* A1i = ws + 12288;
    float* B0r = ws + 16384;    float* B0i = ws + 20480;
    float* B1r = ws + 24576;    float* B1i = ws + 28672;
    int tid = threadIdx.x;
    int d0 = blockIdx.x * 2;
    for (int idx = tid; idx < 4096; idx += 256) {
        int n = idx >> 1, s = idx & 1;
        size_t off = (size_t)(n*2 + s)*DD + d0;
        float2 vr = *(const float2*)(inr + off);
        float2 vi = *(const float2*)(ini + off);
        *(float2*)((s ? A1r : A0r) + n*2) = vr;
        *(float2*)((s ? A1i : A0i) + n*2) = vi;
    }
    __syncthreads();
    float c00r=cr[0], c01r=cr[1], c10r=cr[2], c11r=cr[3];
    float c00i=ci[0], c01i=ci[1], c10i=ci[2], c11i=ci[3];
    bool rc = (c00i==0.f) && (c01i==0.f) && (c10i==0.f) && (c11i==0.f);
    float phi = g_xmean * 0.1f;
    float pc = cosf(phi), ps = sinf(phi);
    int c = tid & 1, nl = tid >> 1;
    int blk = blockIdx.x;
    if (rc) {
        walk_pass<true>(A0r,A0i,A1r,A1i, B0r,B0i,B1r,B1i,
                        c00r,c00i,c01r,c01i,c10r,c10i,c11r,c11i,
                        pc,ps,c,nl,blk, pp1,hp1, true);
        __syncthreads();
        walk_pass<true>(B0r,B0i,B1r,B1i, A0r,A0i,A1r,A1i,
                        c00r,c00i,c01r,c01i,c10r,c10i,c11r,c11i,
                        pc,ps,c,nl,blk, pp2,hp2, false);
    } else {
        walk_pass<false>(A0r,A0i,A1r,A1i, B0r,B0i,B1r,B1i,
                         c00r,c00i,c01r,c01i,c10r,c10i,c11r,c11i,
                         pc,ps,c,nl,blk, pp1,hp1, true);
        __syncthreads();
        walk_pass<false>(B0r,B0i,B1r,B1i, A0r,A0i,A1r,A1i,
                         c00r,c00i,c01r,c01i,c10r,c10i,c11r,c11i,
                         pc,ps,c,nl,blk, pp2,hp2, false);
    }
}

// reduce 512 block-partials per node for BOTH passes. grid (64, 2) x 256.
__global__ void k_pred2(const float* __restrict__ pp1, const float* __restrict__ hp1,
                        const float* __restrict__ pp2, const float* __restrict__ hp2) {
    __shared__ float sp[256], sh[256];
    int tid = threadIdx.x;
    const float* pprt = blockIdx.y ? pp2 : pp1;
    const float* hprt = blockIdx.y ? hp2 : hp1;
    int n = blockIdx.x*32 + (tid & 31);
    int bg = tid >> 5;
    float p = 0.f, h = 0.f;
    for (int j = 0; j < 64; j++) {
        int b = bg*64 + j;
        p += pprt[b*2048 + n];
        h += hprt[b*2048 + n];
    }
    sp[tid] = p; sh[tid] = h; __syncthreads();
    if (tid < 32) {
        float pt = 0.f, ht = 0.f;
#pragma unroll
        for (int g2 = 0; g2 < 8; g2++) { pt += sp[g2*32 + tid]; ht += sh[g2*32 + tid]; }
        if (blockIdx.y) { g_probs2[n] = pt; g_ph2[n] = ht * (1.f/1024.f); }
        else            { g_probs[n]  = pt; g_ph[n]  = ht * (1.f/1024.f); }
    }
}

// both totals in one launch (grid 2)
__global__ void k_ptot2() {
    __shared__ float red[1024];
    int t = threadIdx.x;
    const float* gp = blockIdx.x ? g_probs2 : g_probs;
    red[t] = gp[t] + gp[t + 1024];
    __syncthreads();
    for (int st = 512; st > 0; st >>= 1) {
        if (t < st) red[t] += red[t + st];
        __syncthreads();
    }
    if (t == 0) { if (blockIdx.x) g_ptot2 = red[0]; else g_ptot = red[0]; }
}

// fused double inject: applies step-1 then step-2 transform in registers.
// Exactly equals sequential inject(emb)->cells; inject(cells)->cells.
__global__ void k_inject2(const float* __restrict__ src, float* __restrict__ dst) {
    int i = blockIdx.x, d = threadIdx.x;      // 512 threads
    // step 1 params
    float inv1 = 1.f / (g_ptot + 1e-8f);
    float p1 = g_probs[i] * inv1;
    float in1 = 0.f;
#pragma unroll
    for (int k = 0; k < 6; k++) in1 += p1 - g_probs[i ^ (1 << k)] * inv1;
    in1 *= 0.03f;
    float phc1 = g_ph[i] * 0.3f;
    float c1 = cosf(phc1), s1 = sinf(phc1);
    float sc1 = 0.8f + 0.4f * p1;
    // step 2 params
    float inv2 = 1.f / (g_ptot2 + 1e-8f);
    float p2 = g_probs2[i] * inv2;
    float in2 = 0.f;
#pragma unroll
    for (int k = 0; k < 6; k++) in2 += p2 - g_probs2[i ^ (1 << k)] * inv2;
    in2 *= 0.03f;
    float phc2 = g_ph2[i] * 0.3f;
    float c2 = cosf(phc2), s2 = sinf(phc2);
    float sc2 = 0.8f + 0.4f * p2;

    float t1 = src[i*DD + d]       * sc1;
    float t2 = src[i*DD + HD2 + d] * sc1;
    float u1 = 0.5f*(t1*c1 - t2*s1) + 0.5f*t1 + in1;
    float u2 = 0.5f*(t1*s1 + t2*c1) + 0.5f*t2 + in1;
    float w1 = u1 * sc2;
    float w2 = u2 * sc2;
    dst[i*DD + d]       = 0.5f*(w1*c2 - w2*s2) + 0.5f*w1 + in2;
    dst[i*DD + HD2 + d] = 0.5f*(w1*s2 + w2*c2) + 0.5f*w2 + in2;
}

// smem-resident per-column frustration recurrence; 8 blocks x 128 columns
__global__ void k_frust(const float* __restrict__ fs) {
    extern __shared__ float fsm[];                 // sc[128*128] + sfs[1024]
    float* sc  = fsm;
    float* sfs = fsm + 128*128;
    int t = threadIdx.x;
    int col = blockIdx.x * 128 + t;
    for (int r = 0; r < 128; r++) sc[r*128 + t] = g_cells[r*DD + col];
    for (int i = t; i < 1024; i += 128) sfs[i] = fs[i];
    __syncthreads();
    float p0 = g_cells[128*DD + col];
    float p1 = g_cells[256*DD + col];
    float p2 = g_cells[512*DD + col];
    for (int i = 0; i < 128; i++) {
        float n0=0.f, n1=0.f, n2=0.f;
        if (i + 1 < 128) {
            n0 = g_cells[((i+1)^128)*DD + col];
            n1 = g_cells[((i+1)^256)*DD + col];
            n2 = g_cells[((i+1)^512)*DD + col];
        }
        float fi = sfs[i];
        float infl = fi*(sfs[i^128]*p0 + sfs[i^256]*p1 + sfs[i^512]*p2);
#pragma unroll
        for (int b = 0; b < 7; b++) {
            int j = i ^ (1 << b);
            infl += fi * sfs[j] * sc[j*128 + t];
        }
        sc[i*128 + t] = 0.85f * sc[i*128 + t] + 0.015f * infl;
        p0 = n0; p1 = n1; p2 = n2;
    }
    for (int r = 0; r < 128; r++) g_cells[r*DD + col] = sc[r*128 + t];
}

// morph: wave factor applied at load (runs only when step%3==0)
__global__ void k_morph(const int* __restrict__ step) {
    if (step[0] % 3 != 0) return;
    __shared__ float sv[8*48];
    int t = threadIdx.x;
    int lc = t >> 3, kt = t & 7;
    int col = blockIdx.x * 8 + lc;
    for (int k = kt; k < 48; k += 8)
        sv[lc*48 + k] = __fmul_rn(g_cells[k*DD + col], g_wavef[k]);
    __syncwarp();
    for (int i = 0; i < 48; i++) {
        float vi = sv[lc*48 + i];
        float s = 0.f;
#pragma unroll
        for (int j = 0; j < 6; j++) s += tanhf(sv[lc*48 + kt*6 + j] - vi);
        s += __shfl_down_sync(0xffffffffu, s, 4, 8);
        s += __shfl_down_sync(0xffffffffu, s, 2, 8);
        s += __shfl_down_sync(0xffffffffu, s, 1, 8);
        if (kt == 0) sv[lc*48 + i] = 0.9f * vi + 0.1f * s * (1.f/47.f);
        __syncwarp();
    }
    for (int k = kt; k < 48; k += 8) g_cells[k*DD + col] = sv[lc*48 + k];
}

__global__ void k_fmean(const int* __restrict__ step) {
    int f = blockIdx.x;
    int col = blockIdx.y * 128 + threadIdx.x;
    bool m = (step[0] % 3 == 0);
    float s = 0.f;
    for (int r = 0; r < 256; r++) {
        int row = f*256 + r;
        float wf = (m && row < 48) ? 1.f : g_wavef[row];
        s += __fmul_rn(g_cells[(size_t)row*DD + col], wf);
    }
    g_fmean[f*DD + col] = s * (1.f/256.f);
}

// faction fused with bcast; wave factor applied inline; writes cellsB + cellsR
__global__ void k_faction(const int* __restrict__ step) {
    int n = blockIdx.x;
    int f = n >> 8, r = n & 255;
    bool m = (step[0] % 3 == 0);
    bool debate = (step[0] > 5) && (r < 64);
    float wf = (m && n < 48) ? 1.f : g_wavef[n];
#pragma unroll
    for (int q = 0; q < 4; q++) {
        int col = q * 256 + threadIdx.x;
        float cw = __fmul_rn(g_cells[n*DD + col], wf);
        float v = 0.85f * cw + 0.15f * g_fmean[f*DD + col];
        if (debate) {
            float g = 0.f;
#pragma unroll
            for (int ff = 0; ff < 8; ff++) g += g_fmean[ff*DD + col];
            v = 0.85f * v + 0.15f * (g * 0.125f);
        }
        float v0 = v + 0.1f * g_xproj[col];
        float v1 = v + 0.1f * g_xproj[DD + col];
        g_cellsB[(size_t)n*DD + col]        = v0;
        g_cellsB[(size_t)(NC + n)*DD + col] = v1;
        g_cellsR[(size_t)n*DD + col]        = tfr(v0);
        g_cellsR[(size_t)(NC + n)*DD + col] = tfr(v1);
    }
}

__global__ void k_xproj(const float* __restrict__ x, const float* __restrict__ w,
                        const float* __restrict__ b) {
    int gw   = (blockIdx.x * blockDim.x + threadIdx.x) >> 5;
    int lane = threadIdx.x & 31;
    if (gw >= BB * DD) return;
    int bi = gw / DD, j = gw % DD;
    const float* xr = x + bi * INDIM;
    const float* wr = w + (size_t)j * INDIM;
    float s = 0.f;
    for (int k = lane; k < INDIM; k += 32) s += xr[k] * wr[k];
    for (int o = 16; o > 0; o >>= 1) s += __shfl_down_sync(0xffffffffu, s, o);
    if (lane == 0) g_xproj[gw] = s + b[j];
}

// ------------------------- tf32 tensor-core GEMMs -------------------------
__device__ __forceinline__ void mma8(float* c, const uint32_t* a, const uint32_t* b) {
    asm volatile(
        "mma.sync.aligned.m16n8k8.row.col.f32.tf32.tf32.f32 "
        "{%0,%1,%2,%3},{%4,%5,%6,%7},{%8,%9},{%0,%1,%2,%3};"
        : "+f"(c[0]), "+f"(c[1]), "+f"(c[2]), "+f"(c[3])
        : "r"(a[0]), "r"(a[1]), "r"(a[2]), "r"(a[3]), "r"(b[0]), "r"(b[1]));
}
__device__ __forceinline__ void cpa16(float* dst, const float* src) {
    unsigned d = (unsigned)__cvta_generic_to_shared(dst);
    asm volatile("cp.async.cg.shared.global [%0], [%1], 16;\n" :: "r"(d), "l"(src));
}
__device__ __forceinline__ void cp_commit() { asm volatile("cp.async.commit_group;\n"); }
__device__ __forceinline__ void cp_wait0() { asm volatile("cp.async.wait_group 0;\n"); }

template<bool DOC>
__device__ __forceinline__ uint32_t opnd(float x) {
    return DOC ? f2tf32(x) : __float_as_uint(x);
}

#define AST 40           // smem row stride (floats) for [row][k] tiles
#define BSTN 132         // smem row stride for [k][n] tiles (NN B)
#define NT_STAGE (128*AST*2)
#define NN_STAGE (128*AST + 32*BSTN)

#define LOAD_AFRAG(AS, AF, KC, DOC)                                       \
    _Pragma("unroll")                                                     \
    for (int mt = 0; mt < 4; mt++) {                                      \
        int rb = wm*64 + mt*16 + g;                                       \
        float2 lo = *(const float2*)&(AS)[rb*AST + (KC)];                 \
        float2 hi = *(const float2*)&(AS)[(rb+8)*AST + (KC)];             \
        (AF)[mt][0] = opnd<DOC>(lo.x); (AF)[mt][2] = opnd<DOC>(lo.y);     \
        (AF)[mt][1] = opnd<DOC>(hi.x); (AF)[mt][3] = opnd<DOC>(hi.y);     \
    }

// C = alpha*A@W^T (+bias); EXPO: C = tf32(exp(alpha*acc)); RO: round output.
template<bool CA, bool CB, bool EXPO, bool RO>
__global__ void __launch_bounds__(256, 2) tgemm_nt(
    const float* __restrict__ A, int lda, long soA, long siA,
    const float* __restrict__ W, int ldw, long soW, long siW,
    const float* __restrict__ bias,
    float* __restrict__ C, int ldc, long soC, long siC,
    int inner, int K, float alpha)
{
    extern __shared__ float sm[];
    int z = blockIdx.z;
    int zo = z / inner, zi = z - zo * inner;
    A += (size_t)zo*soA + (size_t)zi*siA;
    W += (size_t)zo*soW + (size_t)zi*siW;
    C += (size_t)zo*soC + (size_t)zi*siC;

    int tid  = threadIdx.x;
    int wid  = tid >> 5, lane = tid & 31;
    int g = lane >> 2, t = lane & 3;
    int wm = wid & 1, wn = wid >> 1;

    int lr = tid >> 3;
    int lc = (tid & 7) << 2;
    const float* Ab = A + (size_t)(blockIdx.y*128 + lr)*lda + lc;
    const float* Wb = W + (size_t)(blockIdx.x*128 + lr)*ldw + lc;

    float acc[4][4][4] = {};
    int KT = K >> 5;

#define NT_LOAD(KT_)                                                      \
    {                                                                     \
        float* a_s = sm + ((KT_)&1)*NT_STAGE;                             \
        float* b_s = a_s + 128*AST;                                       \
        _Pragma("unroll")                                                 \
        for (int i = 0; i < 4; i++) {                                     \
            cpa16(&a_s[(lr + 32*i)*AST + lc], Ab + (size_t)(32*i)*lda + (KT_)*32); \
            cpa16(&b_s[(lr + 32*i)*AST + lc], Wb + (size_t)(32*i)*ldw + (KT_)*32); \
        }                                                                 \
        cp_commit();                                                      \
    }

    NT_LOAD(0);

    for (int kt = 0; kt < KT; kt++) {
        cp_wait0();
        __syncthreads();
        if (kt + 1 < KT) NT_LOAD(kt+1);
        const float* a_s = sm + (kt&1)*NT_STAGE;
        const float* b_s = a_s + 128*AST;
#pragma unroll
        for (int ks = 0; ks < 4; ks++) {
            uint32_t af[4][4], bf[4][2];
            int kc = ks*8 + 2*t;
            LOAD_AFRAG(a_s, af, kc, CA)
#pragma unroll
            for (int nt = 0; nt < 4; nt++) {
                int nb = wn*32 + nt*8 + g;
                float2 bb = *(const float2*)&b_s[nb*AST + kc];
                bf[nt][0] = opnd<CB>(bb.x); bf[nt][1] = opnd<CB>(bb.y);
            }
#pragma unroll
            for (int mt = 0; mt < 4; mt++)
#pragma unroll
                for (int nt = 0; nt < 4; nt++)
                    mma8(acc[mt][nt], af[mt], bf[nt]);
        }
    }

    int row0 = blockIdx.y*128 + wm*64 + g;
    int col0 = blockIdx.x*128 + wn*32 + 2*t;
#pragma unroll
    for (int nt = 0; nt < 4; nt++) {
        int c = col0 + nt*8;
        float2 bv = make_float2(0.f, 0.f);
        if (bias) bv = *(const float2*)&bias[c];
#pragma unroll
        for (int mt = 0; mt < 4; mt++) {
            int r = row0 + mt*16;
            float2 o0, o1;
            if (EXPO) {
                o0.x = tfr(__expf(alpha*acc[mt][nt][0]));
                o0.y = tfr(__expf(alpha*acc[mt][nt][1]));
                o1.x = tfr(__expf(alpha*acc[mt][nt][2]));
                o1.y = tfr(__expf(alpha*acc[mt][nt][3]));
            } else {
                o0.x = alpha*acc[mt][nt][0] + bv.x;  o0.y = alpha*acc[mt][nt][1] + bv.y;
                o1.x = alpha*acc[mt][nt][2] + bv.x;  o1.y = alpha*acc[mt][nt][3] + bv.y;
                if (RO) {
                    o0.x = tfr(o0.x); o0.y = tfr(o0.y);
                    o1.x = tfr(o1.x); o1.y = tfr(o1.y);
                }
            }
            *(float2*)&C[(size_t)r*ldc + c]     = o0;
            *(float2*)&C[(size_t)(r+8)*ldc + c] = o1;
        }
    }
}

// C = A@B, batched. ZC: per-row Z = sum_k A (from smem), scale rows by 1/Z,
// write Z to Zout. RO: round output. Requires grid.x == 1 when ZC.
template<bool CA, bool CB, bool RO, bool ZC>
__global__ void __launch_bounds__(256, 2) tgemm_nn(
    const float* __restrict__ A, int lda, long soA, long siA,
    const float* __restrict__ Bm, int ldb, long soB, long siB,
    float* __restrict__ Zout,
    float* __restrict__ C, int ldc, long soC, long siC,
    int inner, int K)
{
    extern __shared__ float sm[];
    __shared__ float zs[256];
    __shared__ float zfin[128];
    int z = blockIdx.z;
    int zo = z / inner, zi = z - zo * inner;
    A  += (size_t)zo*soA + (size_t)zi*siA;
    Bm += (size_t)zo*soB + (size_t)zi*siB;
    C  += (size_t)zo*soC + (size_t)zi*siC;

    int tid  = threadIdx.x;
    int wid  = tid >> 5, lane = tid & 31;
    int g = lane >> 2, t = lane & 3;
    int wm = wid & 1, wn = wid >> 1;

    int lr = tid >> 3;
    int lc = (tid & 7) << 2;
    const float* Ab = A + (size_t)(blockIdx.y*128 + lr)*lda + lc;
    int br = tid >> 5;
    int bc = (tid & 31) << 2;
    const float* Bb = Bm + blockIdx.x*128 + bc;

    float acc[4][4][4] = {};
    float zacc = 0.f;
    int zr = tid & 127, zh = tid >> 7;
    int KT = K >> 5;

#define NN_LOAD(KT_)                                                      \
    {                                                                     \
        float* a_s = sm + ((KT_)&1)*NN_STAGE;                             \
        float* b_s = a_s + 128*AST;                                       \
        _Pragma("unroll")                                                 \
        for (int i = 0; i < 4; i++) {                                     \
            cpa16(&a_s[(lr + 32*i)*AST + lc], Ab + (size_t)(32*i)*lda + (KT_)*32); \
            cpa16(&b_s[(br + 8*i)*BSTN + bc], Bb + (size_t)((KT_)*32 + br + 8*i)*ldb); \
        }                                                                 \
        cp_commit();                                                      \
    }

    NN_LOAD(0);

    for (int kt = 0; kt < KT; kt++) {
        cp_wait0();
        __syncthreads();
        if (kt + 1 < KT) NN_LOAD(kt+1);
        const float* a_s = sm + (kt&1)*NN_STAGE;
        const float* b_s = a_s + 128*AST;
#pragma unroll
        for (int ks = 0; ks < 4; ks++) {
            uint32_t af[4][4], bf[4][2];
            int kc = ks*8 + 2*t;
            LOAD_AFRAG(a_s, af, kc, CA)
#pragma unroll
            for (int nt = 0; nt < 4; nt++) {
                int nb = wn*32 + nt*8 + g;
                bf[nt][0] = opnd<CB>(b_s[kc*BSTN + nb]);
                bf[nt][1] = opnd<CB>(b_s[(kc+1)*BSTN + nb]);
            }
#pragma unroll
            for (int mt = 0; mt < 4; mt++)
#pragma unroll
                for (int nt = 0; nt < 4; nt++)
                    mma8(acc[mt][nt], af[mt], bf[nt]);
        }
        if (ZC) {
            const float* ap = a_s + zr*AST + zh*16;
#pragma unroll
            for (int j = 0; j < 4; j++) {
                float4 v = *(const float4*)(ap + j*4);
                zacc += v.x + v.y + v.z + v.w;
            }
        }
    }

    if (ZC) {
        zs[tid] = zacc;
        __syncthreads();
        if (tid < 128) {
            float zv = zs[tid] + zs[tid + 128];
            zfin[tid] = 1.f / zv;
            Zout[(size_t)blockIdx.z*NC + blockIdx.y*128 + tid] = zv;
        }
        __syncthreads();
    }

    int row0 = blockIdx.y*128 + wm*64 + g;
    int col0 = blockIdx.x*128 + wn*32 + 2*t;
    float zi0[4], zi1[4];
    if (ZC) {
#pragma unroll
        for (int mt = 0; mt < 4; mt++) {
            zi0[mt] = zfin[wm*64 + mt*16 + g];
            zi1[mt] = zfin[wm*64 + mt*16 + g + 8];
        }
    }
#pragma unroll
    for (int nt = 0; nt < 4; nt++) {
        int c = col0 + nt*8;
#pragma unroll
        for (int mt = 0; mt < 4; mt++) {
            int r = row0 + mt*16;
            float o0 = acc[mt][nt][0], o1 = acc[mt][nt][1];
            float o2 = acc[mt][nt][2], o3 = acc[mt][nt][3];
            if (ZC) { o0 *= zi0[mt]; o1 *= zi0[mt]; o2 *= zi1[mt]; o3 *= zi1[mt]; }
            if (RO) { o0 = tfr(o0); o1 = tfr(o1); o2 = tfr(o2); o3 = tfr(o3); }
            *(float2*)&C[(size_t)r*ldc + c]     = make_float2(o0, o1);
            *(float2*)&C[(size_t)(r+8)*ldc + c] = make_float2(o2, o3);
        }
    }
}

// --------- tension partials: single pass over e, Z from g_rowsum ----------
__global__ void __launch_bounds__(256) k_tens(const float* __restrict__ E) {
    __shared__ float r1[256], r2[256];
    __shared__ float zinv[8];
    int q = blockIdx.x, b = blockIdx.y;
    int tid = threadIdx.x;
    if (tid < 8) zinv[tid] = 0.125f / g_rowsum[(b*8 + tid)*NC + q];
    __syncthreads();
    const float* base = E + (size_t)b*8*NC*NC + (size_t)q*NC;
    const float mu0 = 1.f / 2048.f;
    float zv[8];
#pragma unroll
    for (int h = 0; h < 8; h++) zv[h] = zinv[h];
    float s1 = 0.f, s2 = 0.f;
    for (int k = tid; k < 2048; k += 256) {
        float m = 0.f;
#pragma unroll
        for (int h = 0; h < 8; h++) m += __ldg(&base[(size_t)h*NC*NC + k]) * zv[h];
        s1 += m;
        float d = m - mu0;
        s2 += d * d;
    }
    r1[tid] = s1; r2[tid] = s2; __syncthreads();
    for (int st = 128; st > 0; st >>= 1) {
        if (tid < st) { r1[tid] += r1[tid+st]; r2[tid] += r2[tid+st]; }
        __syncthreads();
    }
    if (tid == 0) { int bq = b*2048 + q; g_part1[bq] = r1[0]; g_part2[bq] = r2[0]; }
}

// outp != nullptr on the final layer: writes tension scalar directly.
__global__ void k_tred(float* outp) {
    __shared__ float r1[1024], r2[1024];
    int t = threadIdx.x;
    float s1 = 0.f, s2 = 0.f;
    for (int i = t; i < BB*NC; i += 1024) { s1 += g_part1[i]; s2 += g_part2[i]; }
    r1[t] = s1; r2[t] = s2; __syncthreads();
    for (int st = 512; st > 0; st >>= 1) {
        if (t < st) { r1[t] += r1[t+st]; r2[t] += r2[t+st]; }
        __syncthreads();
    }
    if (t == 0) {
        double Ne = 8388608.0;
        double S1 = (double)r1[0], D2 = (double)r2[0];
        double mu0 = 1.0 / 2048.0;
        double mu  = S1 / Ne;
        double var = (D2 - Ne * (mu - mu0) * (mu - mu0)) / (Ne - 1.0);
        if (var < 0.0) var = 0.0;
        g_tension += (float)sqrt(var);
        if (outp) outp[0] = g_tension * 0.5f;
    }
}

// addln also writes tf32-rounded copy for the next GEMM's A operand
__global__ void k_addln(const float* __restrict__ g, const float* __restrict__ bta) {
    __shared__ float red[256];
    size_t row = blockIdx.x;
    int t = threadIdx.x;
    float v[4];
    float s = 0.f;
#pragma unroll
    for (int q = 0; q < 4; q++) {
        int d = q * 256 + t;
        v[q] = g_cellsB[row*DD + d] + g_tmp[row*DD + d];
        s += v[q];
    }
    red[t] = s; __syncthreads();
    for (int st = 128; st > 0; st >>= 1) {
        if (t < st) red[t] += red[t + st];
        __syncthreads();
    }
    float mu = red[0] * (1.f/1024.f);
    __syncthreads();
    float s2 = 0.f;
#pragma unroll
    for (int q = 0; q < 4; q++) { float d = v[q] - mu; s2 += d * d; }
    red[t] = s2; __syncthreads();
    for (int st = 128; st > 0; st >>= 1) {
        if (t < st) red[t] += red[t + st];
        __syncthreads();
    }
    float var  = red[0] * (1.f/1024.f);
    float rstd = rsqrtf(var + 1e-5f);
#pragma unroll
    for (int q = 0; q < 4; q++) {
        int d = q * 256 + t;
        float o = (v[q] - mu) * rstd * g[d] + bta[d];
        g_cellsB[row*DD + d] = o;
        g_cellsR[row*DD + d] = tfr(o);
    }
}

// ------------------------------- host launch -------------------------------
extern "C" void kernel_launch(void* const* d_in, const int* in_sizes, int n_in,
                              void* d_out, int out_size) {
    const float* x           = (const float*)d_in[0];
    const float* amp_real    = (const float*)d_in[1];
    const float* amp_imag    = (const float*)d_in[2];
    const float* coin_real   = (const float*)d_in[3];
    const float* coin_imag   = (const float*)d_in[4];
    const float* cell_emb    = (const float*)d_in[5];
    const float* fsigns      = (const float*)d_in[6];
    const float* w_in        = (const float*)d_in[7];
    const float* b_in        = (const float*)d_in[8];
    const float* attn_in_w   = (const float*)d_in[9];
    const float* attn_in_b   = (const float*)d_in[10];
    const float* attn_out_w  = (const float*)d_in[11];
    const float* attn_out_b  = (const float*)d_in[12];
    const float* ln_g        = (const float*)d_in[13];
    const float* ln_b        = (const float*)d_in[14];
    const float* w_out       = (const float*)d_in[15];
    const float* b_out       = (const float*)d_in[16];
    const int*   step        = (const int*)d_in[17];
    float* out = (float*)d_out;

    float *p_ar0, *p_ai0, *p_ar1, *p_ai1, *p_cells, *p_cellsB, *p_cellsR,
          *p_qkv, *p_scores, *p_av, *p_tmp, *p_wqkv, *p_wout, *p_wfin, *p_rowsum;
    cudaGetSymbolAddress((void**)&p_ar0,    g_ampr0);
    cudaGetSymbolAddress((void**)&p_ai0,    g_ampi0);
    cudaGetSymbolAddress((void**)&p_ar1,    g_ampr1);
    cudaGetSymbolAddress((void**)&p_ai1,    g_ampi1);
    cudaGetSymbolAddress((void**)&p_cells,  g_cells);
    cudaGetSymbolAddress((void**)&p_cellsB, g_cellsB);
    cudaGetSymbolAddress((void**)&p_cellsR, g_cellsR);
    cudaGetSymbolAddress((void**)&p_qkv,    g_qkv);
    cudaGetSymbolAddress((void**)&p_scores, g_scores);
    cudaGetSymbolAddress((void**)&p_av,     g_av);
    cudaGetSymbolAddress((void**)&p_tmp,    g_tmp);
    cudaGetSymbolAddress((void**)&p_wqkv,   g_wqkv);
    cudaGetSymbolAddress((void**)&p_wout,   g_wout);
    cudaGetSymbolAddress((void**)&p_wfin,   g_wfin);
    cudaGetSymbolAddress((void**)&p_rowsum, g_rowsum);

    const int nt_smem = NT_STAGE*2*(int)sizeof(float);  // 81920
    const int nn_smem = NN_STAGE*2*(int)sizeof(float);  // 74752
    const int fr_smem = (128*128 + 1024)*(int)sizeof(float); // 69632
    const int ww_smem = 32768*(int)sizeof(float);       // 131072 (dbl-buffered)

    static cudaStream_t sB;
    static cudaEvent_t evF, evB, evA0, evA1, evT0, evT1;
    static int init_done = 0;
    if (!init_done) {
        cudaFuncSetAttribute(tgemm_nt<false,false,false,true>,  cudaFuncAttributeMaxDynamicSharedMemorySize, nt_smem);
        cudaFuncSetAttribute(tgemm_nt<false,false,true,false>,  cudaFuncAttributeMaxDynamicSharedMemorySize, nt_smem);
        cudaFuncSetAttribute(tgemm_nt<false,false,false,false>, cudaFuncAttributeMaxDynamicSharedMemorySize, nt_smem);
        cudaFuncSetAttribute(tgemm_nn<false,false,true,true>,   cudaFuncAttributeMaxDynamicSharedMemorySize, nn_smem);
        cudaFuncSetAttribute(k_frust,  cudaFuncAttributeMaxDynamicSharedMemorySize, fr_smem);
        cudaFuncSetAttribute(k_walk2,  cudaFuncAttributeMaxDynamicSharedMemorySize, ww_smem);
        cudaStreamCreateWithFlags(&sB, cudaStreamNonBlocking);
        cudaEventCreateWithFlags(&evF,  cudaEventDisableTiming);
        cudaEventCreateWithFlags(&evB,  cudaEventDisableTiming);
        cudaEventCreateWithFlags(&evA0, cudaEventDisableTiming);
        cudaEventCreateWithFlags(&evA1, cudaEventDisableTiming);
        cudaEventCreateWithFlags(&evT0, cudaEventDisableTiming);
        cudaEventCreateWithFlags(&evT1, cudaEventDisableTiming);
        init_done = 1;
    }
    cudaEvent_t evA[2] = {evA0, evA1};
    cudaEvent_t evT[2] = {evT0, evT1};

    // ---- fork side stream: weight round-copy + xproj (independent of preamble)
    cudaEventRecord(evF, 0);
    cudaStreamWaitEvent(sB, evF, 0);
    {
        int n4a = 2*D3*DD/4, n4b = 2*DD*DD/4, n4c = INDIM*DD/4;
        k_roundcpy<<<(n4a+255)/256, 256, 0, sB>>>(p_wqkv, attn_in_w, n4a);
        k_roundcpy<<<(n4b+255)/256, 256, 0, sB>>>(p_wout, attn_out_w, n4b);
        k_roundcpy<<<(n4c+255)/256, 256, 0, sB>>>(p_wfin, w_out, n4c);
        k_xproj<<<256, 256, 0, sB>>>(x, w_in, b_in);
    }
    cudaEventRecord(evB, sB);

    // ---- update_cells preamble (main stream, serial) ----
    k_xmean<<<1, 256>>>(x, BB * INDIM);
    k_wavef<<<2, 1024>>>(step);

    // fused double walk: both passes' partials, no amp DRAM round-trip
    k_walk2<<<512, 256, ww_smem>>>(amp_real, amp_imag, coin_real, coin_imag,
                                   p_ar1, p_ai1, p_ar0, p_ai0);
    // both prob/phase reductions + both totals + fused double inject
    k_pred2<<<dim3(64, 2), 256>>>(p_ar1, p_ai1, p_ar0, p_ai0);
    k_ptot2<<<2, 1024>>>();
    k_inject2<<<NC, 512>>>(cell_emb, p_cells);

    k_frust<<<8, 128, fr_smem>>>(fsigns);
    k_morph<<<128, 64>>>(step);
    k_fmean<<<dim3(8, 8), 128>>>(step);

    // join: faction (fused with bcast + wave) needs xproj + wqkv ready
    cudaStreamWaitEvent(0, evB, 0);
    k_faction<<<NC, 256>>>(step);

    float* tens_out = (out_size >= BB*NC*INDIM + 1) ? (out + (size_t)BB*NC*INDIM)
                                                    : (float*)nullptr;

    const float inv_sqrt_hd = 0.0883883476483184f; // 1/sqrt(128)
    for (int l = 0; l < 2; l++) {
        // qkv = cellsR @ Wqkv^T + b : zero-cvt inner loop (A pre-rounded)
        tgemm_nt<false,false,false,true><<<dim3(24, 32, 1), 256, nt_smem>>>(
            p_cellsR, DD, 0, 0,
            p_wqkv + (size_t)l*D3*DD, DD, 0, 0,
            attn_in_b + (size_t)l*D3,
            p_qkv, D3, 0, 0, 1, DD, 1.f);

        // scores -> raw e: layer 2 must wait for layer-1 k_tens (reads g_scores)
        if (l == 1) cudaStreamWaitEvent(0, evT[0], 0);
        tgemm_nt<false,false,true,false><<<dim3(16, 16, 16), 256, nt_smem>>>(
            p_qkv,        D3, (long)NC*D3, 128,
            p_qkv + 1024, D3, (long)NC*D3, 128,
            nullptr,
            p_scores, NC, (long)8*NC*NC, (long)NC*NC,
            8, HDIM, inv_sqrt_hd);

        // av = (e @ V) / Z : Z computed in-kernel; Z -> g_rowsum
        tgemm_nn<false,false,true,true><<<dim3(1, 16, 16), 256, nn_smem>>>(
            p_scores,     NC, (long)8*NC*NC, (long)NC*NC,
            p_qkv + 2048, D3, (long)NC*D3, 128,
            p_rowsum,
            p_av, DD, (long)NC*DD, 128,
            8, NC);

        // tension partials overlap with out-proj/addln/next-qkv on side stream
        cudaEventRecord(evA[l], 0);
        cudaStreamWaitEvent(sB, evA[l], 0);
        k_tens<<<dim3(NC, BB), 256, 0, sB>>>(p_scores);
        k_tred<<<1, 1024, 0, sB>>>(l == 1 ? tens_out : (float*)nullptr);
        cudaEventRecord(evT[l], sB);

        // out-proj: both operands pre-rounded; output exact (residual)
        tgemm_nt<false,false,false,false><<<dim3(8, 32, 1), 256, nt_smem>>>(
            p_av, DD, 0, 0,
            p_wout + (size_t)l*DD*DD, DD, 0, 0,
            attn_out_b + (size_t)l*DD,
            p_tmp, DD, 0, 0, 1, DD, 1.f);

        k_addln<<<BB*NC, 256>>>(ln_g + (size_t)l*DD, ln_b + (size_t)l*DD);
    }

    // final projection: zero-cvt (A pre-rounded via cellsR, B pre-rounded)
    tgemm_nt<false,false,false,false><<<dim3(4, 32, 1), 256, nt_smem>>>(
        p_cellsR, DD, 0, 0,
        p_wfin, DD, 0, 0,
        b_out,
        out, INDIM, 0, 0, 1, DD, 1.f);

    // join side stream back into the capture-origin stream
    cudaStreamWaitEvent(0, evT[1], 0);
}